// round 3
// baseline (speedup 1.0000x reference)
#include <cuda_runtime.h>

#define N_NODES 50000

// Scratch (device globals — no allocation allowed)
__device__ float g_h0[N_NODES * 128];    // layer1 GEMM output
__device__ float g_agg1[N_NODES * 128];  // layer1 aggregation -> becomes h (in place)
__device__ float g_h2[N_NODES * 64];     // layer2 GEMM output
__device__ int   g_cnt_in[N_NODES];      // count of col occurrences
__device__ int   g_cnt_out[N_NODES];     // count of row occurrences

__device__ __forceinline__ void red_add_v4(float* p, float4 v) {
    asm volatile("red.global.add.v4.f32 [%0], {%1, %2, %3, %4};"
                 :: "l"(p), "f"(v.x), "f"(v.y), "f"(v.z), "f"(v.w) : "memory");
}

__global__ void zero_cnt_kernel(int n) {
    int i = blockIdx.x * blockDim.x + threadIdx.x;
    if (i < n) { g_cnt_in[i] = 0; g_cnt_out[i] = 0; }
}

__global__ void degree_kernel(const int* __restrict__ ei, int E) {
    int i = blockIdx.x * blockDim.x + threadIdx.x;
    if (i < E) {
        atomicAdd(&g_cnt_out[ei[i]], 1);      // row occurrences
        atomicAdd(&g_cnt_in[ei[E + i]], 1);   // col occurrences
    }
}

// Y = X @ W^T + B.  Also writes Yinit = Y (self-loop seed of the aggregation).
// X: [n,128], W: [OUTC,128] row-major, B: [OUTC].
// Block = 256 threads = 8 warps; warp handles 4 rows; lane covers OUTC/32 output cols.
template<int OUTC>
__global__ void gemm_kernel(const float* __restrict__ X,
                            const float* __restrict__ W,
                            const float* __restrict__ B,
                            float* __restrict__ Y,
                            float* __restrict__ Yinit,
                            int n) {
    constexpr int INC  = 128;
    constexpr int VEC  = OUTC / 32;
    constexpr int OUTP = OUTC + 4;   // pad: conflict-free transposed stores, 16B-aligned reads
    extern __shared__ float sm[];
    float* Wsm = sm;                 // [INC][OUTP], Wsm[k][j] = W[j][k]
    float* Xs  = sm + INC * OUTP;    // [8 warps][4 rows][INC]

    int tid = threadIdx.x, lane = tid & 31, warp = tid >> 5;

    // Load W transposed into smem. Global read coalesced (consecutive k for one j);
    // smem store stride OUTP=OUTC+4 floats -> banks cycle, no conflict.
    for (int i = tid; i < OUTC * INC; i += blockDim.x) {
        int j = i / INC, k = i - j * INC;
        Wsm[k * OUTP + j] = W[i];
    }
    float bias[VEC];
#pragma unroll
    for (int v = 0; v < VEC; v++) bias[v] = B[lane * VEC + v];
    __syncthreads();

    int rowBase = blockIdx.x * 32 + warp * 4;
    float* xw = Xs + warp * 4 * INC;
#pragma unroll
    for (int r = 0; r < 4; r++) {
        int row = rowBase + r;
        if (row < n)
            ((float4*)(xw + r * INC))[lane] =
                ((const float4*)(X + (size_t)row * INC))[lane];
    }
    __syncwarp();

    float acc[4][VEC];
#pragma unroll
    for (int r = 0; r < 4; r++)
#pragma unroll
        for (int v = 0; v < VEC; v++) acc[r][v] = bias[v];

#pragma unroll 4
    for (int k = 0; k < INC; k++) {
        float wv[VEC];
        if constexpr (VEC == 4) {
            float4 w4 = *(const float4*)(Wsm + k * OUTP + lane * 4);
            wv[0] = w4.x; wv[1] = w4.y; wv[2] = w4.z; wv[3] = w4.w;
        } else {
            float2 w2 = *(const float2*)(Wsm + k * OUTP + lane * 2);
            wv[0] = w2.x; wv[1] = w2.y;
        }
#pragma unroll
        for (int r = 0; r < 4; r++) {
            float xv = xw[r * INC + k];  // broadcast LDS
#pragma unroll
            for (int v = 0; v < VEC; v++) acc[r][v] += xv * wv[v];
        }
    }

#pragma unroll
    for (int r = 0; r < 4; r++) {
        int row = rowBase + r;
        if (row < n) {
            if constexpr (VEC == 4) {
                float4 o = make_float4(acc[r][0], acc[r][1], acc[r][2], acc[r][3]);
                ((float4*)(Y     + (size_t)row * OUTC))[lane] = o;
                ((float4*)(Yinit + (size_t)row * OUTC))[lane] = o;
            } else {
                float2 o = make_float2(acc[r][0], acc[r][1]);
                ((float2*)(Y     + (size_t)row * OUTC))[lane] = o;
                ((float2*)(Yinit + (size_t)row * OUTC))[lane] = o;
            }
        }
    }
}

// Unnormalized scatter-add: dst[didx[e]] += src[sidx[e]] over C floats per edge.
// C=128: 1 warp per edge (lane -> one float4). C=64: 2 edges per warp.
template<int C>
__global__ void scatter_kernel(const int* __restrict__ sidx,
                               const int* __restrict__ didx,
                               const float* __restrict__ src,
                               float* __restrict__ dst, int E) {
    constexpr int LPE = C / 4;        // lanes per edge
    constexpr int EPW = 32 / LPE;     // edges per warp
    int t = blockIdx.x * blockDim.x + threadIdx.x;
    int gw = t >> 5;
    int lane = t & 31;
    int sub = lane / LPE;
    int li = lane - sub * LPE;
    long e = (long)gw * EPW + sub;
    if (e < E) {
        int s = sidx[e], d = didx[e];
        float4 v = ((const float4*)(src + (size_t)s * C))[li];
        red_add_v4(dst + (size_t)d * C + (size_t)li * 4, v);
    }
}

// h = relu(agg1 / (cnt_in+1)), in place. One float4 per thread, C=128 -> 32 f4/node.
__global__ void relu_scale_kernel(int n) {
    int i = blockIdx.x * blockDim.x + threadIdx.x;
    if (i < n * 32) {
        int node = i >> 5;
        float inv = 1.0f / (float)(g_cnt_in[node] + 1);
        float4 v = ((float4*)g_agg1)[i];
        v.x = fmaxf(v.x * inv, 0.0f);
        v.y = fmaxf(v.y * inv, 0.0f);
        v.z = fmaxf(v.z * inv, 0.0f);
        v.w = fmaxf(v.w * inv, 0.0f);
        ((float4*)g_agg1)[i] = v;
    }
}

// out /= (cnt_out+1). C=64 -> 16 f4/node. No relu on layer 2.
__global__ void scale_out_kernel(float* __restrict__ out, int n) {
    int i = blockIdx.x * blockDim.x + threadIdx.x;
    if (i < n * 16) {
        int node = i >> 4;
        float inv = 1.0f / (float)(g_cnt_out[node] + 1);
        float4 v = ((float4*)out)[i];
        v.x *= inv; v.y *= inv; v.z *= inv; v.w *= inv;
        ((float4*)out)[i] = v;
    }
}

extern "C" void kernel_launch(void* const* d_in, const int* in_sizes, int n_in,
                              void* d_out, int out_size) {
    const float* x  = (const float*)d_in[0];
    const int*   ei = (const int*)d_in[1];
    const float* W1 = (const float*)d_in[2];
    const float* b1 = (const float*)d_in[3];
    const float* W2 = (const float*)d_in[4];
    const float* b2 = (const float*)d_in[5];
    float* out = (float*)d_out;

    int n = in_sizes[0] / 128;
    int E = in_sizes[1] / 2;

    float *h0, *agg1, *h2;
    cudaGetSymbolAddress((void**)&h0, g_h0);
    cudaGetSymbolAddress((void**)&agg1, g_agg1);
    cudaGetSymbolAddress((void**)&h2, g_h2);

    int smem1 = (128 * (128 + 4) + 8 * 4 * 128) * (int)sizeof(float); // 83968
    int smem2 = (128 * (64 + 4)  + 8 * 4 * 128) * (int)sizeof(float); // 51200
    cudaFuncSetAttribute(gemm_kernel<128>, cudaFuncAttributeMaxDynamicSharedMemorySize, smem1);
    cudaFuncSetAttribute(gemm_kernel<64>,  cudaFuncAttributeMaxDynamicSharedMemorySize, smem2);

    // 1. zero degree counters (only 400KB — agg buffers seeded by GEMM epilogue)
    zero_cnt_kernel<<<(n + 255) / 256, 256>>>(n);
    // 2. degrees
    degree_kernel<<<(E + 255) / 256, 256>>>(ei, E);
    // 3. h0 = x@W1^T + b1; agg1 seeded with self-loop contribution
    gemm_kernel<128><<<(n + 31) / 32, 256, smem1>>>(x, W1, b1, h0, agg1, n);
    // 4. agg1[col] += h0[row] over all edges
    {
        long threads = (long)E * 32;
        scatter_kernel<128><<<(int)((threads + 255) / 256), 256>>>(ei, ei + E, h0, agg1, E);
    }
    // 5. h = relu(agg1 / in_deg), in place
    relu_scale_kernel<<<(n * 32 + 255) / 256, 256>>>(n);
    // 6. h2 = h@W2^T + b2; out seeded with self-loop contribution
    gemm_kernel<64><<<(n + 31) / 32, 256, smem2>>>(agg1, W2, b2, h2, out, n);
    // 7. flipped edges: out[row] += h2[col]
    {
        long threads = (long)E * 16;
        scatter_kernel<64><<<(int)((threads + 255) / 256), 256>>>(ei + E, ei, h2, out, E);
    }
    // 8. out /= out_deg (in-degree of the flipped graph)
    scale_out_kernel<<<(n * 16 + 255) / 256, 256>>>(out, n);
}

// round 6
// speedup vs baseline: 1.3233x; 1.3233x over previous
#include <cuda_runtime.h>

#define N_NODES 50000
#define MAX_E   900000

// Scratch (device globals — no allocation allowed)
__device__ float g_h0[N_NODES * 128];    // layer1 GEMM output
__device__ float g_h [N_NODES * 128];    // layer1 aggregated+relu output
__device__ float g_h2[N_NODES * 64];     // layer2 GEMM output
__device__ int   g_cnt_in[N_NODES];      // in-degree  (col occurrences)
__device__ int   g_cnt_out[N_NODES];     // out-degree (row occurrences)
__device__ int   g_off_in[N_NODES];      // CSR segment start (by col)
__device__ int   g_off_out[N_NODES];     // CSR segment start (by row)
__device__ int   g_cur_in[N_NODES];      // fill cursors
__device__ int   g_cur_out[N_NODES];
__device__ int   g_csr_in[MAX_E];        // stores src node (row) per in-edge of col
__device__ int   g_csr_out[MAX_E];       // stores dst node (col) per out-edge of row
__device__ int   g_base_in;
__device__ int   g_base_out;

__global__ void zero_cnt_kernel(int n) {
    int i = blockIdx.x * blockDim.x + threadIdx.x;
    if (i < n) { g_cnt_in[i] = 0; g_cnt_out[i] = 0; }
    if (i == 0) { g_base_in = 0; g_base_out = 0; }
}

__global__ void degree_kernel(const int* __restrict__ ei, int E) {
    int i = blockIdx.x * blockDim.x + threadIdx.x;
    if (i < E) {
        atomicAdd(&g_cnt_out[ei[i]], 1);      // row occurrences
        atomicAdd(&g_cnt_in[ei[E + i]], 1);   // col occurrences
    }
}

// Block-local exclusive scan + atomic block base -> CSR segment starts.
// Handles BOTH (in, out) arrays in one launch via blockIdx.y.
// Segment layout across blocks is nondeterministic but output-invariant.
__global__ void offsets_kernel(int n) {
    const int* cnt;
    int *off, *cur, *gbase;
    if (blockIdx.y == 0) { cnt = g_cnt_in;  off = g_off_in;  cur = g_cur_in;  gbase = &g_base_in; }
    else                 { cnt = g_cnt_out; off = g_off_out; cur = g_cur_out; gbase = &g_base_out; }

    __shared__ int wsum[32];
    __shared__ int sbase;
    int tid = threadIdx.x, lane = tid & 31, warp = tid >> 5;
    int v = blockIdx.x * blockDim.x + tid;
    int c = (v < n) ? cnt[v] : 0;
    int val = c;
#pragma unroll
    for (int d = 1; d < 32; d <<= 1) {
        int t = __shfl_up_sync(0xffffffffu, val, d);
        if (lane >= d) val += t;
    }
    if (lane == 31) wsum[warp] = val;
    __syncthreads();
    if (warp == 0) {
        int w = wsum[lane];
#pragma unroll
        for (int d = 1; d < 32; d <<= 1) {
            int t = __shfl_up_sync(0xffffffffu, w, d);
            if (lane >= d) w += t;
        }
        wsum[lane] = w;
    }
    __syncthreads();
    int incl = val + (warp ? wsum[warp - 1] : 0);
    if (tid == blockDim.x - 1) sbase = atomicAdd(gbase, incl);
    __syncthreads();
    if (v < n) {
        int o = sbase + incl - c;   // exclusive
        off[v] = o;
        cur[v] = o;
    }
}

__global__ void fill_kernel(const int* __restrict__ ei, int E) {
    int e = blockIdx.x * blockDim.x + threadIdx.x;
    if (e < E) {
        int r = ei[e], c = ei[E + e];
        int p = atomicAdd(&g_cur_in[c], 1);
        g_csr_in[p] = r;
        int q = atomicAdd(&g_cur_out[r], 1);
        g_csr_out[q] = c;
    }
}

// Y = X @ W^T + B.  X: [n,128], W: [OUTC,128] row-major, B: [OUTC].
// Block = 256 threads = 8 warps; warp handles 4 rows; lane covers OUTC/32 output cols.
template<int OUTC>
__global__ void gemm_kernel(const float* __restrict__ X,
                            const float* __restrict__ W,
                            const float* __restrict__ B,
                            float* __restrict__ Y,
                            int n) {
    constexpr int INC  = 128;
    constexpr int VEC  = OUTC / 32;
    constexpr int OUTP = OUTC + 4;   // pad: conflict-free transposed stores, 16B-aligned reads
    extern __shared__ float sm[];
    float* Wsm = sm;                 // [INC][OUTP], Wsm[k][j] = W[j][k]
    float* Xs  = sm + INC * OUTP;    // [8 warps][4 rows][INC]

    int tid = threadIdx.x, lane = tid & 31, warp = tid >> 5;

    for (int i = tid; i < OUTC * INC; i += blockDim.x) {
        int j = i / INC, k = i - j * INC;
        Wsm[k * OUTP + j] = W[i];
    }
    float bias[VEC];
#pragma unroll
    for (int v = 0; v < VEC; v++) bias[v] = B[lane * VEC + v];
    __syncthreads();

    int rowBase = blockIdx.x * 32 + warp * 4;
    float* xw = Xs + warp * 4 * INC;
#pragma unroll
    for (int r = 0; r < 4; r++) {
        int row = rowBase + r;
        if (row < n)
            ((float4*)(xw + r * INC))[lane] =
                ((const float4*)(X + (size_t)row * INC))[lane];
    }
    __syncwarp();

    float acc[4][VEC];
#pragma unroll
    for (int r = 0; r < 4; r++)
#pragma unroll
        for (int v = 0; v < VEC; v++) acc[r][v] = bias[v];

#pragma unroll 4
    for (int k = 0; k < INC; k++) {
        float wv[VEC];
        if constexpr (VEC == 4) {
            float4 w4 = *(const float4*)(Wsm + k * OUTP + lane * 4);
            wv[0] = w4.x; wv[1] = w4.y; wv[2] = w4.z; wv[3] = w4.w;
        } else {
            float2 w2 = *(const float2*)(Wsm + k * OUTP + lane * 2);
            wv[0] = w2.x; wv[1] = w2.y;
        }
#pragma unroll
        for (int r = 0; r < 4; r++) {
            float xv = xw[r * INC + k];  // broadcast LDS
#pragma unroll
            for (int v = 0; v < VEC; v++) acc[r][v] += xv * wv[v];
        }
    }

#pragma unroll
    for (int r = 0; r < 4; r++) {
        int row = rowBase + r;
        if (row < n) {
            if constexpr (VEC == 4) {
                float4 o = make_float4(acc[r][0], acc[r][1], acc[r][2], acc[r][3]);
                ((float4*)(Y + (size_t)row * OUTC))[lane] = o;
            } else {
                float2 o = make_float2(acc[r][0], acc[r][1]);
                ((float2*)(Y + (size_t)row * OUTC))[lane] = o;
            }
        }
    }
}

// CSR gather-aggregation, fused with normalization (and optional ReLU):
//   dst[v] = act( (src[v] + sum_{e in seg(v)} src[csr[e]]) / (cnt[v]+1) )
// C=128: warp per node (lane -> float4). C=64: 16 lanes per node, 2 nodes/warp.
template<int C, bool RELU>
__global__ void agg_kernel(const float* __restrict__ src,
                           const int* __restrict__ off,
                           const int* __restrict__ cnt,
                           const int* __restrict__ csr,
                           float* __restrict__ dst, int n) {
    constexpr int LPE = C / 4;
    constexpr int NPW = 32 / LPE;
    int t = blockIdx.x * blockDim.x + threadIdx.x;
    int warp = t >> 5, lane = t & 31;
    int sub = lane / LPE, li = lane - sub * LPE;
    int v = warp * NPW + sub;
    if (v >= n) return;

    int beg = off[v];
    int deg = cnt[v];
    int end = beg + deg;

    float4 acc = ((const float4*)(src + (size_t)v * C))[li];  // self loop
    int e = beg;
    for (; e + 4 <= end; e += 4) {
        int s0 = csr[e], s1 = csr[e + 1], s2 = csr[e + 2], s3 = csr[e + 3];
        float4 a = ((const float4*)(src + (size_t)s0 * C))[li];
        float4 b = ((const float4*)(src + (size_t)s1 * C))[li];
        float4 c = ((const float4*)(src + (size_t)s2 * C))[li];
        float4 d = ((const float4*)(src + (size_t)s3 * C))[li];
        float4 p = make_float4(a.x + b.x, a.y + b.y, a.z + b.z, a.w + b.w);
        float4 q = make_float4(c.x + d.x, c.y + d.y, c.z + d.z, c.w + d.w);
        acc.x += p.x + q.x; acc.y += p.y + q.y;
        acc.z += p.z + q.z; acc.w += p.w + q.w;
    }
    for (; e < end; e++) {
        int s = csr[e];
        float4 a = ((const float4*)(src + (size_t)s * C))[li];
        acc.x += a.x; acc.y += a.y; acc.z += a.z; acc.w += a.w;
    }

    float inv = 1.0f / (float)(deg + 1);
    acc.x *= inv; acc.y *= inv; acc.z *= inv; acc.w *= inv;
    if (RELU) {
        acc.x = fmaxf(acc.x, 0.0f); acc.y = fmaxf(acc.y, 0.0f);
        acc.z = fmaxf(acc.z, 0.0f); acc.w = fmaxf(acc.w, 0.0f);
    }
    ((float4*)(dst + (size_t)v * C))[li] = acc;
}

extern "C" void kernel_launch(void* const* d_in, const int* in_sizes, int n_in,
                              void* d_out, int out_size) {
    const float* x  = (const float*)d_in[0];
    const int*   ei = (const int*)d_in[1];
    const float* W1 = (const float*)d_in[2];
    const float* b1 = (const float*)d_in[3];
    const float* W2 = (const float*)d_in[4];
    const float* b2 = (const float*)d_in[5];
    float* out = (float*)d_out;

    int n = in_sizes[0] / 128;
    int E = in_sizes[1] / 2;

    float *h0, *h, *h2;
    int *cnt_in, *cnt_out, *off_in, *off_out, *csr_in, *csr_out;
    cudaGetSymbolAddress((void**)&h0, g_h0);
    cudaGetSymbolAddress((void**)&h,  g_h);
    cudaGetSymbolAddress((void**)&h2, g_h2);
    cudaGetSymbolAddress((void**)&cnt_in,  g_cnt_in);
    cudaGetSymbolAddress((void**)&cnt_out, g_cnt_out);
    cudaGetSymbolAddress((void**)&off_in,  g_off_in);
    cudaGetSymbolAddress((void**)&off_out, g_off_out);
    cudaGetSymbolAddress((void**)&csr_in,  g_csr_in);
    cudaGetSymbolAddress((void**)&csr_out, g_csr_out);

    int smem1 = (128 * (128 + 4) + 8 * 4 * 128) * (int)sizeof(float); // 83968
    int smem2 = (128 * (64 + 4)  + 8 * 4 * 128) * (int)sizeof(float); // 51200
    cudaFuncSetAttribute(gemm_kernel<128>, cudaFuncAttributeMaxDynamicSharedMemorySize, smem1);
    cudaFuncSetAttribute(gemm_kernel<64>,  cudaFuncAttributeMaxDynamicSharedMemorySize, smem2);

    // ---- CSR build ----
    zero_cnt_kernel<<<(n + 255) / 256, 256>>>(n);
    degree_kernel<<<(E + 255) / 256, 256>>>(ei, E);
    {
        dim3 grid((n + 1023) / 1024, 2);
        offsets_kernel<<<grid, 1024>>>(n);
    }
    fill_kernel<<<(E + 255) / 256, 256>>>(ei, E);

    // ---- Layer 1: h0 = x@W1^T + b1 ; h = relu(agg(h0) / in_deg) ----
    gemm_kernel<128><<<(n + 31) / 32, 256, smem1>>>(x, W1, b1, h0, n);
    {
        long threads = (long)n * 32;           // NPW=1 for C=128
        agg_kernel<128, true><<<(int)((threads + 511) / 512), 512>>>(h0, off_in, cnt_in, csr_in, h, n);
    }

    // ---- Layer 2 (flipped edges): h2 = h@W2^T + b2 ; out = agg(h2) / out_deg ----
    gemm_kernel<64><<<(n + 31) / 32, 256, smem2>>>(h, W2, b2, h2, n);
    {
        long threads = ((long)n + 1) / 2 * 32; // NPW=2 for C=64
        agg_kernel<64, false><<<(int)((threads + 511) / 512), 512>>>(h2, off_out, cnt_out, csr_out, out, n);
    }
}